// round 6
// baseline (speedup 1.0000x reference)
#include <cuda_runtime.h>
#include <cstdint>

// Problem constants  (V,E,H,T = 32000, 512, 1024, 4096)
#define EMB    512
#define T_SEQ  4096
#define HID    1024
#define G4H    4096          // 4*HID
#define VOC    32000
#define NBLK   128           // recurrence blocks (co-resident, 1/SM)
#define NSTEPS (2*T_SEQ - 1) // 4096 encoder + 4095 decoder = 8191

// ---------------- device scratch (static: no runtime allocation) ----------------
__device__ float g_ih_enc[(size_t)T_SEQ * G4H];       // 64 MB
__device__ float g_ih_dec[(size_t)(T_SEQ-1) * G4H];   // 64 MB
__device__ float g_hs[(size_t)(T_SEQ-1) * HID];       // 16.8 MB
__device__ unsigned long long g_slots[2 * HID];       // (tag,value) pairs, double-buffered
__device__ unsigned int g_ctr;

// ---------------- single-instruction 64-bit generic accesses ----------------
__device__ __forceinline__ void slot_store(unsigned long long* p, unsigned long long v) {
    asm volatile("st.relaxed.gpu.b64 [%0], %1;" :: "l"(p), "l"(v) : "memory");
}
__device__ __forceinline__ unsigned long long slot_load(const unsigned long long* p) {
    unsigned long long v;
    asm volatile("ld.relaxed.gpu.b64 %0, [%1];" : "=l"(v) : "l"(p) : "memory");
    return v;
}
__device__ __forceinline__ unsigned ctr_load(const unsigned* p) {
    unsigned v;
    asm volatile("ld.relaxed.gpu.u32 %0, [%1];" : "=r"(v) : "l"(p) : "memory");
    return v;
}

// ---------------- packed f32x2 helpers (Blackwell; bit-equivalence vs FFMA
// empirically confirmed in R1-vs-R3 A/B) ----------------
__device__ __forceinline__ unsigned long long pack2f(float x) {
    unsigned long long r;
    asm("mov.b64 %0, {%1, %1};" : "=l"(r) : "f"(x));
    return r;
}
__device__ __forceinline__ void ffma2(unsigned long long& d, unsigned long long a, unsigned long long b) {
    asm("fma.rn.f32x2 %0, %1, %2, %0;" : "+l"(d) : "l"(a), "l"(b));
}
__device__ __forceinline__ float lo2(unsigned long long v) { return __uint_as_float((unsigned)v); }
__device__ __forceinline__ float hi2(unsigned long long v) { return __uint_as_float((unsigned)(v >> 32)); }

// ---------------- init kernel (reset sync state each launch) ----------------
__global__ void init_kernel() {
    int i = blockIdx.x * blockDim.x + threadIdx.x;
    if (i < 2 * HID) g_slots[i] = ~0ull;   // tag never matches a real step
    if (i == 0) g_ctr = 0u;
}

// ---------------- NT GEMM: C[M,N] = Arow(m) . B[n,:] + bias1[n] (+bias2[n]) ----
// 128x128 tile, 256 threads, 8x8 micro-tile in packed f32x2 accumulators.
// A rows: if gidx != null, row m = tab[gidx[m]] (length K), else A + m*K.
// K: runtime, multiple of 16. N multiple of 128. M guarded.
#define BM 128
#define BN 128
#define BKT 16
#define PAD 132

__global__ __launch_bounds__(256, 2)
void gemm_nt(const float* __restrict__ A, const float* __restrict__ tab,
             const int* __restrict__ gidx, const float* __restrict__ B,
             const float* __restrict__ bias1, const float* __restrict__ bias2,
             float* __restrict__ C, int M, int N, int K)
{
    __shared__ float As[BKT][PAD];
    __shared__ float Bs[BKT][PAD];
    __shared__ int sidx[BM];

    const int tid = threadIdx.x;
    const int bm = blockIdx.y, bn = blockIdx.x;
    const int row0 = bm * BM;

    if (gidx && tid < BM) {
        int r = row0 + tid; if (r >= M) r = M - 1;
        sidx[tid] = gidx[r];
    }
    __syncthreads();

    const int tx = tid & 15, ty = tid >> 4;

    unsigned long long acc[8][4];
#pragma unroll
    for (int i = 0; i < 8; i++)
#pragma unroll
        for (int j = 0; j < 4; j++) acc[i][j] = 0ull;

    for (int kt = 0; kt < K / BKT; kt++) {
#pragma unroll
        for (int t = 0; t < 2; t++) {
            int idx  = tid + t * 256;       // 0..511
            int arow = idx >> 2;            // 0..127
            int kq   = idx & 3;             // float4 within the 16-wide k tile
            int grow = row0 + arow; if (grow >= M) grow = M - 1;
            const float* ap = gidx ? (tab + (size_t)sidx[arow] * K)
                                   : (A + (size_t)grow * K);
            float4 v = *(const float4*)(ap + kt * BKT + kq * 4);
            As[kq * 4 + 0][arow] = v.x; As[kq * 4 + 1][arow] = v.y;
            As[kq * 4 + 2][arow] = v.z; As[kq * 4 + 3][arow] = v.w;

            int brow = bn * BN + arow;      // N multiple of 128 -> valid
            float4 w = *(const float4*)(B + (size_t)brow * K + kt * BKT + kq * 4);
            Bs[kq * 4 + 0][arow] = w.x; Bs[kq * 4 + 1][arow] = w.y;
            Bs[kq * 4 + 2][arow] = w.z; Bs[kq * 4 + 3][arow] = w.w;
        }
        __syncthreads();

#pragma unroll
        for (int kk = 0; kk < BKT; kk++) {
            float4 a0 = *(const float4*)&As[kk][ty * 4];
            float4 a1 = *(const float4*)&As[kk][64 + ty * 4];
            const unsigned long long* bu = (const unsigned long long*)&Bs[kk][0];
            unsigned long long b0 = bu[tx * 2],      b1 = bu[tx * 2 + 1];
            unsigned long long b2 = bu[32 + tx * 2], b3 = bu[32 + tx * 2 + 1];
            float am[8] = {a0.x, a0.y, a0.z, a0.w, a1.x, a1.y, a1.z, a1.w};
#pragma unroll
            for (int i = 0; i < 8; i++) {
                unsigned long long aa = pack2f(am[i]);
                ffma2(acc[i][0], aa, b0);
                ffma2(acc[i][1], aa, b1);
                ffma2(acc[i][2], aa, b2);
                ffma2(acc[i][3], aa, b3);
            }
        }
        __syncthreads();
    }

    // epilogue
    const int ncol0 = bn * BN + tx * 4;
    const int ncol1 = bn * BN + 64 + tx * 4;
    float bv[8];
#pragma unroll
    for (int j = 0; j < 4; j++) { bv[j] = bias1[ncol0 + j]; bv[4 + j] = bias1[ncol1 + j]; }
    if (bias2) {
#pragma unroll
        for (int j = 0; j < 4; j++) { bv[j] += bias2[ncol0 + j]; bv[4 + j] += bias2[ncol1 + j]; }
    }
#pragma unroll
    for (int i = 0; i < 8; i++) {
        int mloc = (i < 4) ? (ty * 4 + i) : (64 + ty * 4 + (i - 4));
        int m = row0 + mloc;
        if (m < M) {
            float* cp = C + (size_t)m * N;
            float4 o0, o1;
            o0.x = lo2(acc[i][0]) + bv[0]; o0.y = hi2(acc[i][0]) + bv[1];
            o0.z = lo2(acc[i][1]) + bv[2]; o0.w = hi2(acc[i][1]) + bv[3];
            o1.x = lo2(acc[i][2]) + bv[4]; o1.y = hi2(acc[i][2]) + bv[5];
            o1.z = lo2(acc[i][3]) + bv[6]; o1.w = hi2(acc[i][3]) + bv[7];
            *(float4*)(cp + ncol0) = o0;
            *(float4*)(cp + ncol1) = o1;
        }
    }
}

// ---------------- persistent recurrence kernel (simple mapping) ----------------
// Block b owns h elements [8b, 8b+8) -> 32 gate rows. Warp w = gate row:
// gi = w>>3, jj = w&7, global Whh row grow = gi*1024 + 8b + jj.
// Lane l owns columns {l, l+32, ..., l+992}; full-warp shuffle reduce -> part[w].

__global__ __launch_bounds__(1024, 1)
void recurrence(const float* __restrict__ encWhh, const float* __restrict__ decWhh)
{
    __shared__ float hs_sh[HID];
    __shared__ float part[32];
    __shared__ float c_sh[8];

    const int tid = threadIdx.x;
    const int b = blockIdx.x;
    const int w = tid >> 5, l = tid & 31;
    const int gi = w >> 3, jrow = w & 7;
    const int grow = gi * HID + 8 * b + jrow;

    float Wreg[32];
    {
        const float* rp = encWhh + (size_t)grow * HID;
#pragma unroll
        for (int c = 0; c < 32; c++) Wreg[c] = __ldg(rp + l + 32 * c);
    }
    if (tid < 8) c_sh[tid] = 0.0f;
    __syncthreads();

    for (int sc = 0; sc < NSTEPS; sc++) {
        if (sc == T_SEQ) {   // switch to decoder weights (registers only)
            const float* rp = decWhh + (size_t)grow * HID;
#pragma unroll
            for (int c = 0; c < 32; c++) Wreg[c] = __ldg(rp + l + 32 * c);
        }
        const bool enc = sc < T_SEQ;
        const int tstep = enc ? sc : sc - T_SEQ;
        const float* ihb = enc ? g_ih_enc : g_ih_dec;

        // prefetch input-gate values (hidden under sync wait)
        float ih4[4] = {0.f, 0.f, 0.f, 0.f};
        if (tid < 8) {
            const float* ip = ihb + (size_t)tstep * G4H + 8 * b + tid;
#pragma unroll
            for (int g = 0; g < 4; g++) ih4[g] = __ldg(ip + g * HID);
        }

        // --- acquire h(sc-1) ---
        float hval;
        if (sc == 0) {
            hval = 0.0f;
        } else {
            if (tid == 0) {
                unsigned want = 128u * (unsigned)sc;   // all blocks done with step sc-1
                while (ctr_load(&g_ctr) < want) { }
            }
            __syncthreads();
            const unsigned long long* sp = &g_slots[((sc - 1) & 1) * HID + tid];
            unsigned wantTag = (unsigned)(sc - 1);
            unsigned long long v;
            do { v = slot_load(sp); } while ((unsigned)(v >> 32) != wantTag);
            hval = __uint_as_float((unsigned)v);
        }
        hs_sh[tid] = hval;
        __syncthreads();

        // --- (Whh @ h)[grow]: stride-32 lane partials, warp reduce ---
        float s = 0.0f;
#pragma unroll
        for (int c = 0; c < 32; c++) s = fmaf(Wreg[c], hs_sh[l + 32 * c], s);
#pragma unroll
        for (int off = 16; off; off >>= 1) s += __shfl_xor_sync(0xffffffffu, s, off);
        if (l == 0) part[w] = s;
        __syncthreads();

        // --- finalize: gates, cell update, publish h ---
        if (tid < 8) {
            float pi = part[0  + tid] + ih4[0];
            float pf = part[8  + tid] + ih4[1];
            float pg = part[16 + tid] + ih4[2];
            float po = part[24 + tid] + ih4[3];
            float ig = 1.0f / (1.0f + expf(-pi));
            float fg = 1.0f / (1.0f + expf(-pf));
            float gg = tanhf(pg);
            float og = 1.0f / (1.0f + expf(-po));
            float c  = fg * c_sh[tid] + ig * gg;
            c_sh[tid] = c;
            float h  = og * tanhf(c);
            if (!enc) g_hs[(size_t)tstep * HID + 8 * b + tid] = h;
            unsigned long long pv = ((unsigned long long)(unsigned)sc << 32)
                                  | (unsigned long long)__float_as_uint(h);
            slot_store(&g_slots[(sc & 1) * HID + 8 * b + tid], pv);
            __syncwarp(0x000000ffu);
            if (tid == 0) atomicAdd(&g_ctr, 1u);   // throttle; tags carry correctness
        }
    }
}

// ---------------- launch ----------------
extern "C" void kernel_launch(void* const* d_in, const int* in_sizes, int n_in,
                              void* d_out, int out_size)
{
    const int*   seq     = (const int*)  d_in[0];
    const float* enc_emb = (const float*)d_in[1];   // [V, 512]
    const float* enc_Wih = (const float*)d_in[2];   // [4H, 512]
    const float* enc_Whh = (const float*)d_in[3];   // [4H, 1024]
    const float* enc_bih = (const float*)d_in[4];
    const float* enc_bhh = (const float*)d_in[5];
    const float* dec_emb = (const float*)d_in[6];
    const float* dec_Wih = (const float*)d_in[7];
    const float* dec_Whh = (const float*)d_in[8];
    const float* dec_bih = (const float*)d_in[9];
    const float* dec_bhh = (const float*)d_in[10];
    const float* out_W   = (const float*)d_in[11];  // [V, 1024]
    const float* out_b   = (const float*)d_in[12];
    float* out = (float*)d_out;

    float *ih_enc, *ih_dec, *hsbuf;
    cudaGetSymbolAddress((void**)&ih_enc, g_ih_enc);
    cudaGetSymbolAddress((void**)&ih_dec, g_ih_dec);
    cudaGetSymbolAddress((void**)&hsbuf,  g_hs);

    init_kernel<<<2, 1024>>>();

    // Precompute input gates: ih[t] = Wih @ emb[seq[t]] + bih + bhh   (K = EMB = 512!)
    gemm_nt<<<dim3(G4H / 128, T_SEQ / 128), 256>>>(
        nullptr, enc_emb, seq, enc_Wih, enc_bih, enc_bhh, ih_enc, T_SEQ, G4H, EMB);
    gemm_nt<<<dim3(G4H / 128, (T_SEQ - 1 + 127) / 128), 256>>>(
        nullptr, dec_emb, seq, dec_Wih, dec_bih, dec_bhh, ih_dec, T_SEQ - 1, G4H, EMB);

    // Sequential encoder+decoder scan (persistent, cross-SM h exchange through L2)
    recurrence<<<NBLK, 1024>>>(enc_Whh, dec_Whh);

    // Vocab projection: logits = hs @ out_W^T + out_b  -> d_out [4095, 1, 32000]  (K = HID)
    gemm_nt<<<dim3(VOC / 128, (T_SEQ - 1 + 127) / 128), 256>>>(
        hsbuf, nullptr, nullptr, out_W, out_b, nullptr, out, T_SEQ - 1, VOC, HID);
}

// round 7
// speedup vs baseline: 1.0985x; 1.0985x over previous
#include <cuda_runtime.h>
#include <cstdint>

// Problem constants  (V,E,H,T = 32000, 512, 1024, 4096)
#define EMB    512
#define T_SEQ  4096
#define HID    1024
#define G4H    4096          // 4*HID
#define VOC    32000
#define NBLK   128           // recurrence blocks (co-resident, 1/SM)
#define NSTEPS (2*T_SEQ - 1) // 4096 encoder + 4095 decoder = 8191

// ---------------- device scratch (static: no runtime allocation) ----------------
__device__ float g_ih_enc[(size_t)T_SEQ * G4H];       // 64 MB
__device__ float g_ih_dec[(size_t)(T_SEQ-1) * G4H];   // 64 MB
__device__ float g_hs[(size_t)(T_SEQ-1) * HID];       // 16.8 MB
__device__ unsigned long long g_slots[2 * HID];       // (tag,value) pairs, double-buffered

// ---------------- single-instruction 64-bit generic accesses ----------------
__device__ __forceinline__ void slot_store(unsigned long long* p, unsigned long long v) {
    asm volatile("st.relaxed.gpu.b64 [%0], %1;" :: "l"(p), "l"(v) : "memory");
}
__device__ __forceinline__ unsigned long long slot_load(const unsigned long long* p) {
    unsigned long long v;
    asm volatile("ld.relaxed.gpu.b64 %0, [%1];" : "=l"(v) : "l"(p) : "memory");
    return v;
}

// ---------------- packed f32x2 helpers (bit-equivalence vs FFMA confirmed R1-vs-R3) ----
__device__ __forceinline__ unsigned long long pack2f(float x) {
    unsigned long long r;
    asm("mov.b64 %0, {%1, %1};" : "=l"(r) : "f"(x));
    return r;
}
__device__ __forceinline__ void ffma2(unsigned long long& d, unsigned long long a, unsigned long long b) {
    asm("fma.rn.f32x2 %0, %1, %2, %0;" : "+l"(d) : "l"(a), "l"(b));
}
__device__ __forceinline__ float lo2(unsigned long long v) { return __uint_as_float((unsigned)v); }
__device__ __forceinline__ float hi2(unsigned long long v) { return __uint_as_float((unsigned)(v >> 32)); }

// fast sigmoid/tanh via MUFU (__expf); error ~1e-6, budget is 1e-3
__device__ __forceinline__ float sigm_f(float x) { return __frcp_rn(1.0f + __expf(-x)); }
__device__ __forceinline__ float tanh_f(float x) { return 2.0f * __frcp_rn(1.0f + __expf(-2.0f * x)) - 1.0f; }

// ---------------- init kernel (reset sync state each launch) ----------------
__global__ void init_kernel() {
    int i = blockIdx.x * blockDim.x + threadIdx.x;
    if (i < 2 * HID) g_slots[i] = ~0ull;   // tag never matches a real step
}

// ---------------- NT GEMM: C[M,N] = Arow(m) . B[n,:] + bias1[n] (+bias2[n]) ----
// 128x128 tile, 256 threads, 8x8 micro-tile in packed f32x2 accumulators.
// A rows: if gidx != null, row m = tab[gidx[m]] (length K), else A + m*K.
// K: runtime, multiple of 16. N multiple of 128. M guarded.
#define BM 128
#define BN 128
#define BKT 16
#define PAD 132

__global__ __launch_bounds__(256, 2)
void gemm_nt(const float* __restrict__ A, const float* __restrict__ tab,
             const int* __restrict__ gidx, const float* __restrict__ B,
             const float* __restrict__ bias1, const float* __restrict__ bias2,
             float* __restrict__ C, int M, int N, int K)
{
    __shared__ float As[BKT][PAD];
    __shared__ float Bs[BKT][PAD];
    __shared__ int sidx[BM];

    const int tid = threadIdx.x;
    const int bm = blockIdx.y, bn = blockIdx.x;
    const int row0 = bm * BM;

    if (gidx && tid < BM) {
        int r = row0 + tid; if (r >= M) r = M - 1;
        sidx[tid] = gidx[r];
    }
    __syncthreads();

    const int tx = tid & 15, ty = tid >> 4;

    unsigned long long acc[8][4];
#pragma unroll
    for (int i = 0; i < 8; i++)
#pragma unroll
        for (int j = 0; j < 4; j++) acc[i][j] = 0ull;

    for (int kt = 0; kt < K / BKT; kt++) {
#pragma unroll
        for (int t = 0; t < 2; t++) {
            int idx  = tid + t * 256;       // 0..511
            int arow = idx >> 2;            // 0..127
            int kq   = idx & 3;             // float4 within the 16-wide k tile
            int grow = row0 + arow; if (grow >= M) grow = M - 1;
            const float* ap = gidx ? (tab + (size_t)sidx[arow] * K)
                                   : (A + (size_t)grow * K);
            float4 v = *(const float4*)(ap + kt * BKT + kq * 4);
            As[kq * 4 + 0][arow] = v.x; As[kq * 4 + 1][arow] = v.y;
            As[kq * 4 + 2][arow] = v.z; As[kq * 4 + 3][arow] = v.w;

            int brow = bn * BN + arow;      // N multiple of 128 -> valid
            float4 w = *(const float4*)(B + (size_t)brow * K + kt * BKT + kq * 4);
            Bs[kq * 4 + 0][arow] = w.x; Bs[kq * 4 + 1][arow] = w.y;
            Bs[kq * 4 + 2][arow] = w.z; Bs[kq * 4 + 3][arow] = w.w;
        }
        __syncthreads();

#pragma unroll
        for (int kk = 0; kk < BKT; kk++) {
            float4 a0 = *(const float4*)&As[kk][ty * 4];
            float4 a1 = *(const float4*)&As[kk][64 + ty * 4];
            const unsigned long long* bu = (const unsigned long long*)&Bs[kk][0];
            unsigned long long b0 = bu[tx * 2],      b1 = bu[tx * 2 + 1];
            unsigned long long b2 = bu[32 + tx * 2], b3 = bu[32 + tx * 2 + 1];
            float am[8] = {a0.x, a0.y, a0.z, a0.w, a1.x, a1.y, a1.z, a1.w};
#pragma unroll
            for (int i = 0; i < 8; i++) {
                unsigned long long aa = pack2f(am[i]);
                ffma2(acc[i][0], aa, b0);
                ffma2(acc[i][1], aa, b1);
                ffma2(acc[i][2], aa, b2);
                ffma2(acc[i][3], aa, b3);
            }
        }
        __syncthreads();
    }

    // epilogue
    const int ncol0 = bn * BN + tx * 4;
    const int ncol1 = bn * BN + 64 + tx * 4;
    float bv[8];
#pragma unroll
    for (int j = 0; j < 4; j++) { bv[j] = bias1[ncol0 + j]; bv[4 + j] = bias1[ncol1 + j]; }
    if (bias2) {
#pragma unroll
        for (int j = 0; j < 4; j++) { bv[j] += bias2[ncol0 + j]; bv[4 + j] += bias2[ncol1 + j]; }
    }
#pragma unroll
    for (int i = 0; i < 8; i++) {
        int mloc = (i < 4) ? (ty * 4 + i) : (64 + ty * 4 + (i - 4));
        int m = row0 + mloc;
        if (m < M) {
            float* cp = C + (size_t)m * N;
            float4 o0, o1;
            o0.x = lo2(acc[i][0]) + bv[0]; o0.y = hi2(acc[i][0]) + bv[1];
            o0.z = lo2(acc[i][1]) + bv[2]; o0.w = hi2(acc[i][1]) + bv[3];
            o1.x = lo2(acc[i][2]) + bv[4]; o1.y = hi2(acc[i][2]) + bv[5];
            o1.z = lo2(acc[i][3]) + bv[6]; o1.w = hi2(acc[i][3]) + bv[7];
            *(float4*)(cp + ncol0) = o0;
            *(float4*)(cp + ncol1) = o1;
        }
    }
}

// ---------------- persistent recurrence kernel ----------------
// Block b owns h elements [8b, 8b+8) -> 32 gate rows. Warp w = gate row:
// gi = w>>3, jj = w&7, global Whh row grow = gi*1024 + 8b + jj.
// Lane l owns columns {l, l+32, ..., l+992}; warp shuffle reduce -> part[w].
// Sync: pure tag-polling on double-buffered (tag|h) u64 slots in L2.
// Deadlock-free without a counter: tag s is overwritten only at step s+2,
// which transitively requires all blocks to have consumed tag s.

__global__ __launch_bounds__(1024, 1)
void recurrence(const float* __restrict__ encWhh, const float* __restrict__ decWhh)
{
    __shared__ float hs_sh[HID];
    __shared__ float part[32];
    __shared__ float c_sh[8];

    const int tid = threadIdx.x;
    const int b = blockIdx.x;
    const int w = tid >> 5, l = tid & 31;
    const int gi = w >> 3, jrow = w & 7;
    const int grow = gi * HID + 8 * b + jrow;

    float Wreg[32];
    {
        const float* rp = encWhh + (size_t)grow * HID;
#pragma unroll
        for (int c = 0; c < 32; c++) Wreg[c] = __ldg(rp + l + 32 * c);
    }
    if (tid < 8) c_sh[tid] = 0.0f;
    __syncthreads();

    for (int sc = 0; sc < NSTEPS; sc++) {
        if (sc == T_SEQ) {   // switch to decoder weights (registers only)
            const float* rp = decWhh + (size_t)grow * HID;
#pragma unroll
            for (int c = 0; c < 32; c++) Wreg[c] = __ldg(rp + l + 32 * c);
        }
        const bool enc = sc < T_SEQ;
        const int tstep = enc ? sc : sc - T_SEQ;
        const float* ihb = enc ? g_ih_enc : g_ih_dec;

        // prefetch input-gate values (hidden under the tag poll)
        float ih4[4] = {0.f, 0.f, 0.f, 0.f};
        if (tid < 8) {
            const float* ip = ihb + (size_t)tstep * G4H + 8 * b + tid;
#pragma unroll
            for (int g = 0; g < 4; g++) ih4[g] = __ldg(ip + g * HID);
        }

        // --- acquire h(sc-1): direct tag poll, no counter gate ---
        float hval;
        if (sc == 0) {
            hval = 0.0f;
        } else {
            const unsigned long long* sp = &g_slots[((sc - 1) & 1) * HID + tid];
            const unsigned wantTag = (unsigned)(sc - 1);
            unsigned long long v = slot_load(sp);
            while ((unsigned)(v >> 32) != wantTag) v = slot_load(sp);
            hval = __uint_as_float((unsigned)v);
        }
        hs_sh[tid] = hval;
        __syncthreads();

        // --- (Whh @ h)[grow]: 4 independent accumulators + warp reduce ---
        float s0 = 0.f, s1 = 0.f, s2 = 0.f, s3 = 0.f;
#pragma unroll
        for (int c = 0; c < 8; c++) {
            s0 = fmaf(Wreg[4*c + 0], hs_sh[l + 32 * (4*c + 0)], s0);
            s1 = fmaf(Wreg[4*c + 1], hs_sh[l + 32 * (4*c + 1)], s1);
            s2 = fmaf(Wreg[4*c + 2], hs_sh[l + 32 * (4*c + 2)], s2);
            s3 = fmaf(Wreg[4*c + 3], hs_sh[l + 32 * (4*c + 3)], s3);
        }
        float s = (s0 + s1) + (s2 + s3);
#pragma unroll
        for (int off = 16; off; off >>= 1) s += __shfl_xor_sync(0xffffffffu, s, off);
        if (l == 0) part[w] = s;
        __syncthreads();

        // --- finalize: gates, cell update, publish h ---
        if (tid < 8) {
            float pi = part[0  + tid] + ih4[0];
            float pf = part[8  + tid] + ih4[1];
            float pg = part[16 + tid] + ih4[2];
            float po = part[24 + tid] + ih4[3];
            float ig = sigm_f(pi);
            float fg = sigm_f(pf);
            float gg = tanh_f(pg);
            float og = sigm_f(po);
            float c  = fg * c_sh[tid] + ig * gg;
            c_sh[tid] = c;
            float h  = og * tanh_f(c);
            if (!enc) g_hs[(size_t)tstep * HID + 8 * b + tid] = h;
            unsigned long long pv = ((unsigned long long)(unsigned)sc << 32)
                                  | (unsigned long long)__float_as_uint(h);
            slot_store(&g_slots[(sc & 1) * HID + 8 * b + tid], pv);
        }
        // next iteration's poll + barrier protect hs_sh/part reuse
    }
}

// ---------------- launch ----------------
extern "C" void kernel_launch(void* const* d_in, const int* in_sizes, int n_in,
                              void* d_out, int out_size)
{
    const int*   seq     = (const int*)  d_in[0];
    const float* enc_emb = (const float*)d_in[1];   // [V, 512]
    const float* enc_Wih = (const float*)d_in[2];   // [4H, 512]
    const float* enc_Whh = (const float*)d_in[3];   // [4H, 1024]
    const float* enc_bih = (const float*)d_in[4];
    const float* enc_bhh = (const float*)d_in[5];
    const float* dec_emb = (const float*)d_in[6];
    const float* dec_Wih = (const float*)d_in[7];
    const float* dec_Whh = (const float*)d_in[8];
    const float* dec_bih = (const float*)d_in[9];
    const float* dec_bhh = (const float*)d_in[10];
    const float* out_W   = (const float*)d_in[11];  // [V, 1024]
    const float* out_b   = (const float*)d_in[12];
    float* out = (float*)d_out;

    float *ih_enc, *ih_dec, *hsbuf;
    cudaGetSymbolAddress((void**)&ih_enc, g_ih_enc);
    cudaGetSymbolAddress((void**)&ih_dec, g_ih_dec);
    cudaGetSymbolAddress((void**)&hsbuf,  g_hs);

    init_kernel<<<2, 1024>>>();

    // Precompute input gates: ih[t] = Wih @ emb[seq[t]] + bih + bhh   (K = EMB = 512)
    gemm_nt<<<dim3(G4H / 128, T_SEQ / 128), 256>>>(
        nullptr, enc_emb, seq, enc_Wih, enc_bih, enc_bhh, ih_enc, T_SEQ, G4H, EMB);
    gemm_nt<<<dim3(G4H / 128, (T_SEQ - 1 + 127) / 128), 256>>>(
        nullptr, dec_emb, seq, dec_Wih, dec_bih, dec_bhh, ih_dec, T_SEQ - 1, G4H, EMB);

    // Sequential encoder+decoder scan (persistent, cross-SM h exchange through L2)
    recurrence<<<NBLK, 1024>>>(enc_Whh, dec_Whh);

    // Vocab projection: logits = hs @ out_W^T + out_b  -> d_out [4095, 1, 32000]  (K = HID)
    gemm_nt<<<dim3(VOC / 128, (T_SEQ - 1 + 127) / 128), 256>>>(
        hsbuf, nullptr, nullptr, out_W, out_b, nullptr, out, T_SEQ - 1, VOC, HID);
}